// round 17
// baseline (speedup 1.0000x reference)
#include <cuda_runtime.h>
#include <cuda_bf16.h>
#include <cstdint>

#define D       128
#define N_SRC   200000
#define N_MID   50000
#define N_DST   10000
#define E1      800000
#define E2      160000

typedef unsigned long long u64t;

#define SCAN_CHUNK 2048
#define NB1 ((N_MID + SCAN_CHUNK - 1) / SCAN_CHUNK)   // 25
#define NB2 ((N_DST + SCAN_CHUNK - 1) / SCAN_CHUNK)   // 5

// ---- scratch (static device globals; no runtime allocation) ----
__device__ int   g_cnt1[N_MID + SCAN_CHUNK];
__device__ int   g_off1[NB1 * SCAN_CHUNK];
__device__ int   g_bsum1[32];
__device__ int   g_eidx1[E1];
__device__ int   g_slot1[E1];
__device__ int   g_cnt2[N_DST + SCAN_CHUNK];
__device__ int   g_off2[NB2 * SCAN_CHUNK];
__device__ int   g_bsum2[32];
__device__ int   g_eidx2[E2];
__device__ int   g_slot2[E2];
__device__ float g_agg[N_MID * D];
__device__ float g_h[N_MID * D];

// ======================= CSR build (exact R16) =========================
__global__ void hist_slot(const int* __restrict__ col,
                          int* __restrict__ cnt,
                          int* __restrict__ slot, int E) {
    int i = blockIdx.x * blockDim.x + threadIdx.x;
    if (i < E) slot[i] = atomicAdd(&cnt[col[i]], 1);
}

__global__ void __launch_bounds__(256, 4)
scan_partial(const int* __restrict__ cnt, int* __restrict__ off,
             int* __restrict__ bsum) {
    __shared__ int wsum[8];
    const int t = threadIdx.x, lane = t & 31, w = t >> 5;
    const int base = blockIdx.x * SCAN_CHUNK + t * 8;

    int4 a = *(const int4*)(cnt + base);
    int4 b = *(const int4*)(cnt + base + 4);
    int v[8] = {a.x, a.y, a.z, a.w, b.x, b.y, b.z, b.w};
    int s = 0;
    #pragma unroll
    for (int j = 0; j < 8; j++) s += v[j];

    int x = s;
    #pragma unroll
    for (int d = 1; d < 32; d <<= 1) {
        int y = __shfl_up_sync(0xffffffffu, x, d);
        if (lane >= d) x += y;
    }
    if (lane == 31) wsum[w] = x;
    __syncthreads();
    if (t < 8) {
        int ws = wsum[t];
        int p = 0;
        #pragma unroll
        for (int q = 0; q < 8; q++) {
            int val = __shfl_sync(0xffu, ws, q);
            if (q < t) p += val;
        }
        wsum[t] = p;
    }
    __syncthreads();

    int run = (x - s) + wsum[w];
    int o[8];
    #pragma unroll
    for (int j = 0; j < 8; j++) { o[j] = run; run += v[j]; }
    *(int4*)(off + base)     = make_int4(o[0], o[1], o[2], o[3]);
    *(int4*)(off + base + 4) = make_int4(o[4], o[5], o[6], o[7]);
    if (t == 255) bsum[blockIdx.x] = run;
}

__device__ __forceinline__ int warp_bsum_excl(const int* __restrict__ bsum,
                                              int nb) {
    int lane = threadIdx.x & 31;
    int v = (lane < nb) ? bsum[lane] : 0;
    int x = v;
    #pragma unroll
    for (int d = 1; d < 32; d <<= 1) {
        int y = __shfl_up_sync(0xffffffffu, x, d);
        if (lane >= d) x += y;
    }
    return x - v;
}

__global__ void place_scatter(const int* __restrict__ row,
                              const int* __restrict__ col,
                              const int* __restrict__ slot,
                              const int* __restrict__ off,
                              const int* __restrict__ bsum, int nb,
                              int* __restrict__ eidx, int E) {
    int excl = warp_bsum_excl(bsum, nb);
    int i = blockIdx.x * blockDim.x + threadIdx.x;
    if (i < E) {
        int c = col[i];
        int base = off[c] + __shfl_sync(0xffffffffu, excl, c >> 11);
        eidx[base + slot[i]] = row[i];
    }
}

// ======================= aggregation (exact R16) ========================
__global__ void __launch_bounds__(256)
agg_kernel(const float* __restrict__ xsrc,
           const int* __restrict__ off,
           const int* __restrict__ bsum, int nb,
           const int* __restrict__ eidx,
           float* __restrict__ agg, int n) {
    const int excl = warp_bsum_excl(bsum, nb);
    int c    = (blockIdx.x * blockDim.x + threadIdx.x) >> 5;
    int lane = threadIdx.x & 31;
    if (c >= n) return;
    int s = off[c]     + __shfl_sync(0xffffffffu, excl, c >> 11);
    int e = off[c + 1] + __shfl_sync(0xffffffffu, excl, (c + 1) >> 11);

    float4 acc = make_float4(0.f, 0.f, 0.f, 0.f);
    int i = s;
    for (; i + 4 <= e; i += 4) {
        int r0 = eidx[i + 0], r1 = eidx[i + 1];
        int r2 = eidx[i + 2], r3 = eidx[i + 3];
        float4 v0 = ((const float4*)(xsrc + (size_t)r0 * D))[lane];
        float4 v1 = ((const float4*)(xsrc + (size_t)r1 * D))[lane];
        float4 v2 = ((const float4*)(xsrc + (size_t)r2 * D))[lane];
        float4 v3 = ((const float4*)(xsrc + (size_t)r3 * D))[lane];
        acc.x += (v0.x + v1.x) + (v2.x + v3.x);
        acc.y += (v0.y + v1.y) + (v2.y + v3.y);
        acc.z += (v0.z + v1.z) + (v2.z + v3.z);
        acc.w += (v0.w + v1.w) + (v2.w + v3.w);
    }
    for (; i < e; i++) {
        int r = eidx[i];
        float4 v = ((const float4*)(xsrc + (size_t)r * D))[lane];
        acc.x += v.x; acc.y += v.y; acc.z += v.z; acc.w += v.w;
    }
    float invd = (e > s) ? 1.0f / (float)(e - s) : 0.f;
    acc.x *= invd; acc.y *= invd; acc.z *= invd; acc.w *= invd;
    ((float4*)(agg + (size_t)c * D))[lane] = acc;
}

// ===================== mma.sync helpers (exact R16) ====================
__device__ __forceinline__ uint32_t smem_u32(const void* p) {
    uint32_t a;
    asm("{ .reg .u64 t; cvta.to.shared.u64 t, %1; cvt.u32.u64 %0, t; }"
        : "=r"(a) : "l"(p));
    return a;
}
__device__ __forceinline__ void ldsm_x4(uint32_t& r0, uint32_t& r1,
                                        uint32_t& r2, uint32_t& r3,
                                        uint32_t addr) {
    asm volatile("ldmatrix.sync.aligned.m8n8.x4.shared.b16 {%0,%1,%2,%3}, [%4];"
                 : "=r"(r0), "=r"(r1), "=r"(r2), "=r"(r3) : "r"(addr));
}
__device__ __forceinline__ void ldsm_x2(uint32_t& r0, uint32_t& r1,
                                        uint32_t addr) {
    asm volatile("ldmatrix.sync.aligned.m8n8.x2.shared.b16 {%0,%1}, [%2];"
                 : "=r"(r0), "=r"(r1) : "r"(addr));
}
__device__ __forceinline__ void mma_bf16(float* d, const uint32_t* a,
                                         const uint32_t* b) {
    asm volatile(
        "mma.sync.aligned.m16n8k16.row.col.f32.bf16.bf16.f32 "
        "{%0,%1,%2,%3}, {%4,%5,%6,%7}, {%8,%9}, {%0,%1,%2,%3};"
        : "+f"(d[0]), "+f"(d[1]), "+f"(d[2]), "+f"(d[3])
        : "r"(a[0]), "r"(a[1]), "r"(a[2]), "r"(a[3]), "r"(b[0]), "r"(b[1]));
}

static __device__ __forceinline__ uint32_t pack_hi(float x, float y) {
    unsigned short hx = __bfloat16_as_ushort(__float2bfloat16(x));
    unsigned short hy = __bfloat16_as_ushort(__float2bfloat16(y));
    return (uint32_t)hx | ((uint32_t)hy << 16);
}
static __device__ __forceinline__ uint32_t pack_lo(float x, float y) {
    float rx = x - __bfloat162float(__float2bfloat16(x));
    float ry = y - __bfloat162float(__float2bfloat16(y));
    unsigned short lx = __bfloat16_as_ushort(__float2bfloat16(rx));
    unsigned short ly = __bfloat16_as_ushort(__float2bfloat16(ry));
    return (uint32_t)lx | ((uint32_t)ly << 16);
}

// ========== tensor-core SAGE layer, M=64 tile -> 2 CTAs/SM ============
// Per CTA: 64-row tile; warp w owns cols [16w,16w+16), mf loops 4 row
// fragments. Two K=128 phases share fp32 accumulators (lin_l + lin_r).
#define TILE_M 64
#define LDAB2 272
#define SMA_HI 0
#define SMA_LO (TILE_M * LDAB2)             // 17408
#define SMB_HI (2 * TILE_M * LDAB2)         // 34816
#define SMB_LO (SMB_HI + 128 * LDAB2)       // 69632
#define SM_BIAS (SMB_LO + 128 * LDAB2)      // 104448
#define SM_PART (SM_BIAS + 512)             // 104960 (8*64 floats)
#define SM_INVN (SM_PART + 2048)            // 107008
#define MMA_SMEM_BYTES (SM_INVN + 256)      // 107264 -> 2 CTAs/SM

// stage 64 A rows (fp32 -> bf16 hi/lo): row = tid>>2, quarter = tid&3.
__device__ __forceinline__ void stage_a64(const float* __restrict__ src,
                                          char* sm, int tid,
                                          int tileBase, int n) {
    int row = tid >> 2, q = tid & 3;
    int grow = tileBase + row;
    bool valid = grow < n;
    const float4* p = (const float4*)(src + (size_t)grow * D + q * 32);
    uint32_t* hi = (uint32_t*)(sm + SMA_HI + row * LDAB2 + q * 64);
    uint32_t* lo = (uint32_t*)(sm + SMA_LO + row * LDAB2 + q * 64);
    #pragma unroll
    for (int i = 0; i < 8; i++) {
        float4 v = valid ? p[i] : make_float4(0.f, 0.f, 0.f, 0.f);
        hi[2 * i]     = pack_hi(v.x, v.y);
        hi[2 * i + 1] = pack_hi(v.z, v.w);
        lo[2 * i]     = pack_lo(v.x, v.y);
        lo[2 * i + 1] = pack_lo(v.z, v.w);
    }
}

// stage 128 W rows (row = tid>>1, half = tid&1), same as R16.
__device__ __forceinline__ void stage_b(const float* __restrict__ src,
                                        char* sm, int tid) {
    int row = tid >> 1, half = tid & 1;
    const float4* p = (const float4*)(src + (size_t)row * D + half * 64);
    uint32_t* hi = (uint32_t*)(sm + SMB_HI + row * LDAB2 + half * 128);
    uint32_t* lo = (uint32_t*)(sm + SMB_LO + row * LDAB2 + half * 128);
    #pragma unroll
    for (int i = 0; i < 16; i++) {
        float4 v = p[i];
        hi[2 * i]     = pack_hi(v.x, v.y);
        hi[2 * i + 1] = pack_hi(v.z, v.w);
        lo[2 * i]     = pack_lo(v.x, v.y);
        lo[2 * i + 1] = pack_lo(v.z, v.w);
    }
}

__device__ __forceinline__ void mma_phase(float acc[4][2][4],
                                          uint32_t a_addr0, uint32_t b_addr0) {
    #pragma unroll 1
    for (int ks = 0; ks < 8; ks++) {
        uint32_t k0b = (uint32_t)(ks * 32);
        uint32_t bh0[2], bl0[2], bh1[2], bl1[2];
        ldsm_x2(bh0[0], bh0[1], b_addr0 + SMB_HI + k0b);
        ldsm_x2(bl0[0], bl0[1], b_addr0 + SMB_LO + k0b);
        ldsm_x2(bh1[0], bh1[1], b_addr0 + SMB_HI + 8 * LDAB2 + k0b);
        ldsm_x2(bl1[0], bl1[1], b_addr0 + SMB_LO + 8 * LDAB2 + k0b);
        #pragma unroll
        for (int mf = 0; mf < 4; mf++) {
            uint32_t arow = (uint32_t)(mf * 16 * LDAB2) + k0b;
            uint32_t ah[4], al[4];
            ldsm_x4(ah[0], ah[1], ah[2], ah[3], a_addr0 + SMA_HI + arow);
            ldsm_x4(al[0], al[1], al[2], al[3], a_addr0 + SMA_LO + arow);
            mma_bf16(acc[mf][0], ah, bh0);
            mma_bf16(acc[mf][0], ah, bl0);
            mma_bf16(acc[mf][0], al, bh0);
            mma_bf16(acc[mf][1], ah, bh1);
            mma_bf16(acc[mf][1], ah, bl1);
            mma_bf16(acc[mf][1], al, bh1);
        }
    }
}

template <bool RELU>
__global__ void __launch_bounds__(256, 2)
sage_mma(const float* __restrict__ agg,
         const float* __restrict__ xdst,
         const float* __restrict__ Wl, const float* __restrict__ bl,
         const float* __restrict__ Wr,
         float* __restrict__ out, int n) {
    extern __shared__ char sm[];
    const uint32_t sbase = smem_u32(sm);
    const int tid  = threadIdx.x;
    const int lane = tid & 31;
    const int w    = tid >> 5;
    const int tileBase = blockIdx.x * TILE_M;

    float* sBias = (float*)(sm + SM_BIAS);
    float* sPart = (float*)(sm + SM_PART);
    float* sInv  = (float*)(sm + SM_INVN);

    const uint32_t a_addr0 = sbase +
        (uint32_t)((lane & 15) * LDAB2 + (lane >> 4) * 16);
    const uint32_t b_addr0 = sbase +
        (uint32_t)((w * 16 + (lane & 7)) * LDAB2 + ((lane >> 3) & 1) * 16);

    stage_a64(agg, sm, tid, tileBase, n);
    stage_b(Wl, sm, tid);
    if (tid < 128) sBias[tid] = bl[tid];
    __syncthreads();

    float acc[4][2][4];
    #pragma unroll
    for (int mf = 0; mf < 4; mf++)
        #pragma unroll
        for (int nf = 0; nf < 2; nf++)
            acc[mf][nf][0] = acc[mf][nf][1] = acc[mf][nf][2] = acc[mf][nf][3] = 0.f;

    mma_phase(acc, a_addr0, b_addr0);
    __syncthreads();

    stage_a64(xdst, sm, tid, tileBase, n);
    stage_b(Wr, sm, tid);
    __syncthreads();

    mma_phase(acc, a_addr0, b_addr0);

    // ---- bias ----
    #pragma unroll
    for (int mf = 0; mf < 4; mf++)
        #pragma unroll
        for (int nf = 0; nf < 2; nf++) {
            int colb = w * 16 + nf * 8 + 2 * (lane & 3);
            float b0 = sBias[colb], b1 = sBias[colb + 1];
            acc[mf][nf][0] += b0; acc[mf][nf][1] += b1;
            acc[mf][nf][2] += b0; acc[mf][nf][3] += b1;
        }

    // ---- per-warp partial row sums of squares ----
    #pragma unroll
    for (int mf = 0; mf < 4; mf++) {
        float s0 = acc[mf][0][0] * acc[mf][0][0] + acc[mf][0][1] * acc[mf][0][1]
                 + acc[mf][1][0] * acc[mf][1][0] + acc[mf][1][1] * acc[mf][1][1];
        float s1 = acc[mf][0][2] * acc[mf][0][2] + acc[mf][0][3] * acc[mf][0][3]
                 + acc[mf][1][2] * acc[mf][1][2] + acc[mf][1][3] * acc[mf][1][3];
        s0 += __shfl_xor_sync(0xffffffffu, s0, 1);
        s0 += __shfl_xor_sync(0xffffffffu, s0, 2);
        s1 += __shfl_xor_sync(0xffffffffu, s1, 1);
        s1 += __shfl_xor_sync(0xffffffffu, s1, 2);
        if ((lane & 3) == 0) {
            sPart[w * TILE_M + mf * 16 + (lane >> 2)]     = s0;
            sPart[w * TILE_M + mf * 16 + (lane >> 2) + 8] = s1;
        }
    }
    __syncthreads();
    if (tid < TILE_M) {
        float tot = 0.f;
        #pragma unroll
        for (int ww = 0; ww < 8; ww++) tot += sPart[ww * TILE_M + tid];
        sInv[tid] = 1.0f / fmaxf(sqrtf(tot), 1e-12f);
    }
    __syncthreads();

    // ---- normalize, (ReLU), store ----
    #pragma unroll
    for (int mf = 0; mf < 4; mf++) {
        int r0l = mf * 16 + (lane >> 2);
        int grow0 = tileBase + r0l;
        int grow1 = grow0 + 8;
        float inv0 = sInv[r0l], inv1 = sInv[r0l + 8];
        #pragma unroll
        for (int nf = 0; nf < 2; nf++) {
            int col = w * 16 + nf * 8 + 2 * (lane & 3);
            float v0 = acc[mf][nf][0] * inv0, v1 = acc[mf][nf][1] * inv0;
            float v2 = acc[mf][nf][2] * inv1, v3 = acc[mf][nf][3] * inv1;
            if (RELU) {
                v0 = fmaxf(v0, 0.f); v1 = fmaxf(v1, 0.f);
                v2 = fmaxf(v2, 0.f); v3 = fmaxf(v3, 0.f);
            }
            if (grow0 < n)
                *(float2*)(out + (size_t)grow0 * D + col) = make_float2(v0, v1);
            if (grow1 < n)
                *(float2*)(out + (size_t)grow1 * D + col) = make_float2(v2, v3);
        }
    }
}

// ---------------------------------------------------------------------
// Launch sequence — exact R16 (memset zeroing, main chain first so agg1
// stays at the sampled kernel index as a control).
// ---------------------------------------------------------------------
extern "C" void kernel_launch(void* const* d_in, const int* in_sizes, int n_in,
                              void* d_out, int out_size) {
    const float* x    = (const float*)d_in[0];
    const float* Wl1  = (const float*)d_in[1];
    const float* bl1  = (const float*)d_in[2];
    const float* Wr1  = (const float*)d_in[3];
    const float* Wl2  = (const float*)d_in[4];
    const float* bl2  = (const float*)d_in[5];
    const float* Wr2  = (const float*)d_in[6];
    const int*   row1 = (const int*)d_in[7];
    const int*   col1 = (const int*)d_in[8];
    const int*   row2 = (const int*)d_in[9];
    const int*   col2 = (const int*)d_in[10];
    float* out = (float*)d_out;

    int *cnt1, *off1, *bsum1, *eidx1, *slot1;
    int *cnt2, *off2, *bsum2, *eidx2, *slot2;
    float *agg, *h;
    cudaGetSymbolAddress((void**)&cnt1, g_cnt1);
    cudaGetSymbolAddress((void**)&off1, g_off1);
    cudaGetSymbolAddress((void**)&bsum1, g_bsum1);
    cudaGetSymbolAddress((void**)&eidx1, g_eidx1);
    cudaGetSymbolAddress((void**)&slot1, g_slot1);
    cudaGetSymbolAddress((void**)&cnt2, g_cnt2);
    cudaGetSymbolAddress((void**)&off2, g_off2);
    cudaGetSymbolAddress((void**)&bsum2, g_bsum2);
    cudaGetSymbolAddress((void**)&eidx2, g_eidx2);
    cudaGetSymbolAddress((void**)&slot2, g_slot2);
    cudaGetSymbolAddress((void**)&agg, g_agg);
    cudaGetSymbolAddress((void**)&h,   g_h);

    cudaFuncSetAttribute(sage_mma<true>,
                         cudaFuncAttributeMaxDynamicSharedMemorySize,
                         MMA_SMEM_BYTES);
    cudaFuncSetAttribute(sage_mma<false>,
                         cudaFuncAttributeMaxDynamicSharedMemorySize,
                         MMA_SMEM_BYTES);

    static cudaStream_t s_side = nullptr;
    static cudaEvent_t  s_ev0  = nullptr, s_ev1 = nullptr;
    if (!s_side) {
        cudaStreamCreateWithFlags(&s_side, cudaStreamNonBlocking);
        cudaEventCreateWithFlags(&s_ev0, cudaEventDisableTiming);
        cudaEventCreateWithFlags(&s_ev1, cudaEventDisableTiming);
    }

    cudaMemsetAsync(cnt1, 0, (N_MID + SCAN_CHUNK) * sizeof(int), 0);
    cudaMemsetAsync(cnt2, 0, (N_DST + SCAN_CHUNK) * sizeof(int), 0);
    cudaEventRecord(s_ev0, 0);

    // ---- main chain first (agg1 = sampled kernel index 3) ----
    hist_slot<<<(E1 + 255) / 256, 256>>>(col1, cnt1, slot1, E1);
    scan_partial<<<NB1, 256>>>(cnt1, off1, bsum1);
    place_scatter<<<(E1 + 255) / 256, 256>>>(row1, col1, slot1,
                                             off1, bsum1, NB1, eidx1, E1);
    agg_kernel<<<(N_MID * 32 + 255) / 256, 256>>>(x, off1, bsum1, NB1,
                                                  eidx1, agg, N_MID);

    // ---- side: CSR2 build (concurrent from the fork) ----
    cudaStreamWaitEvent(s_side, s_ev0, 0);
    hist_slot<<<(E2 + 255) / 256, 256, 0, s_side>>>(col2, cnt2, slot2, E2);
    scan_partial<<<NB2, 256, 0, s_side>>>(cnt2, off2, bsum2);
    place_scatter<<<(E2 + 255) / 256, 256, 0, s_side>>>(row2, col2, slot2,
                                                        off2, bsum2, NB2,
                                                        eidx2, E2);
    cudaEventRecord(s_ev1, s_side);

    // ---- main: finish layer 1, join, layer 2 ----
    sage_mma<true><<<(N_MID + TILE_M - 1) / TILE_M, 256, MMA_SMEM_BYTES>>>(
        agg, x, Wl1, bl1, Wr1, h, N_MID);
    cudaStreamWaitEvent(0, s_ev1, 0);
    agg_kernel<<<(N_DST * 32 + 255) / 256, 256>>>(h, off2, bsum2, NB2,
                                                  eidx2, agg, N_DST);
    sage_mma<false><<<(N_DST + TILE_M - 1) / TILE_M, 256, MMA_SMEM_BYTES>>>(
        agg, h, Wl2, bl2, Wr2, out, N_DST);
}